// round 16
// baseline (speedup 1.0000x reference)
#include <cuda_runtime.h>
#include <cuda_bf16.h>
#include <cuda_fp16.h>
#include <math.h>

#define Bb   2
#define Ss   4096
#define Gg   256
#define Hh   4
#define DKk  64
#define DIMd 768
#define EXP2K (0.125f * 1.44269504088896341f)
#define VSCALE 4096.0f
#define OSCALE (1.0f / 4096.0f)
#define NSG (Bb * Ss * Gg)
#define WN (Gg * Gg)

// ---------------- scratch ----------------
__device__ __half         g_x16[2 * NSG];
__device__ __nv_bfloat16  g_xvh[NSG];
__device__ __nv_bfloat16  g_xvl[NSG];
__device__ __half         g_w16[2 * WN];
__device__ __nv_bfloat16  g_wvh[2 * WN];
__device__ __nv_bfloat16  g_wvl[2 * WN];
__device__ __half g_q16[NSG];
__device__ __half g_k16[NSG];
__device__ float  g_v  [NSG];
__device__ __half g_p[(size_t)Bb * Hh * Ss * Ss];
__device__ float g_part[(size_t)Bb * Hh * 128 * Ss];
__device__ __half g_vt[Bb * Hh * DKk * Ss];
__device__ __nv_bfloat16 g_atth[NSG];
__device__ __nv_bfloat16 g_attl[NSG];

// ---------------- helpers ----------------
__device__ __forceinline__ unsigned smem_u32(const void* p) {
    unsigned a;
    asm("{ .reg .u64 t; cvta.to.shared.u64 t, %1; cvt.u32.u64 %0, t; }" : "=r"(a) : "l"(p));
    return a;
}
__device__ __forceinline__ float ex2f(float x) {
    float r;
    asm("ex2.approx.ftz.f32 %0, %1;" : "=f"(r) : "f"(x));
    return r;
}
__device__ __forceinline__ void ldsm4(unsigned& r0, unsigned& r1, unsigned& r2,
                                      unsigned& r3, unsigned addr) {
    asm volatile("ldmatrix.sync.aligned.m8n8.x4.shared.b16 {%0,%1,%2,%3}, [%4];"
                 : "=r"(r0), "=r"(r1), "=r"(r2), "=r"(r3) : "r"(addr));
}
__device__ __forceinline__ void mma_bf16(float* c, const unsigned* a, const unsigned* b) {
    asm volatile(
        "mma.sync.aligned.m16n8k16.row.col.f32.bf16.bf16.f32 "
        "{%0,%1,%2,%3},{%4,%5,%6,%7},{%8,%9},{%0,%1,%2,%3};"
        : "+f"(c[0]), "+f"(c[1]), "+f"(c[2]), "+f"(c[3])
        : "r"(a[0]), "r"(a[1]), "r"(a[2]), "r"(a[3]), "r"(b[0]), "r"(b[1]));
}
__device__ __forceinline__ void mma_f16(float* c, const unsigned* a, const unsigned* b) {
    asm volatile(
        "mma.sync.aligned.m16n8k16.row.col.f32.f16.f16.f32 "
        "{%0,%1,%2,%3},{%4,%5,%6,%7},{%8,%9},{%0,%1,%2,%3};"
        : "+f"(c[0]), "+f"(c[1]), "+f"(c[2]), "+f"(c[3])
        : "r"(a[0]), "r"(a[1]), "r"(a[2]), "r"(a[3]), "r"(b[0]), "r"(b[1]));
}
__device__ __forceinline__ void split2(float a, float b, unsigned& h, unsigned& l) {
    __nv_bfloat162 h2 = __floats2bfloat162_rn(a, b);
    __nv_bfloat162 l2 = __floats2bfloat162_rn(a - __bfloat162float(h2.x),
                                              b - __bfloat162float(h2.y));
    h = *reinterpret_cast<unsigned*>(&h2);
    l = *reinterpret_cast<unsigned*>(&l2);
}

// ---------------- fused split kernel ----------------
__global__ __launch_bounds__(256) void split_all_kernel(
    const float* __restrict__ x,
    const float* __restrict__ w0, const float* __restrict__ w1,
    const float* __restrict__ w2, const float* __restrict__ w3,
    __half* __restrict__ x16,
    __nv_bfloat16* __restrict__ xvh, __nv_bfloat16* __restrict__ xvl,
    __half* __restrict__ w16,
    __nv_bfloat16* __restrict__ wvh, __nv_bfloat16* __restrict__ wvl)
{
    if (blockIdx.x < 6144) {
        const int i = blockIdx.x * 256 + threadIdx.x;
        float4 f = reinterpret_cast<const float4*>(x)[i];
        const int row = i / 192, c4 = i - row * 192;
        const int slice = c4 >> 6, w4 = c4 & 63;
        if (slice < 2) {
            const size_t o = (size_t)slice * NSG + (size_t)row * Gg + w4 * 4;
            uint2 hv;
            __half2 a = __floats2half2_rn(f.x, f.y);
            __half2 b2 = __floats2half2_rn(f.z, f.w);
            hv.x = *reinterpret_cast<unsigned*>(&a);
            hv.y = *reinterpret_cast<unsigned*>(&b2);
            *reinterpret_cast<uint2*>(x16 + o) = hv;
        } else {
            const size_t o = (size_t)row * Gg + w4 * 4;
            uint2 hv, lv;
            split2(f.x, f.y, hv.x, lv.x);
            split2(f.z, f.w, hv.y, lv.y);
            *reinterpret_cast<uint2*>(xvh + o) = hv;
            *reinterpret_cast<uint2*>(xvl + o) = lv;
        }
    } else {
        const int bi = blockIdx.x - 6144;
        const int z = bi >> 6;
        const int i = (bi & 63) * 256 + threadIdx.x;
        const float* src = (z == 0) ? w0 : (z == 1) ? w1 : (z == 2) ? w2 : w3;
        float4 f = reinterpret_cast<const float4*>(src)[i];
        if (z < 2) {
            uint2 hv;
            __half2 a = __floats2half2_rn(f.x, f.y);
            __half2 b2 = __floats2half2_rn(f.z, f.w);
            hv.x = *reinterpret_cast<unsigned*>(&a);
            hv.y = *reinterpret_cast<unsigned*>(&b2);
            *reinterpret_cast<uint2*>(w16 + (size_t)z * WN + (size_t)i * 4) = hv;
        } else {
            uint2 hv, lv;
            split2(f.x, f.y, hv.x, lv.x);
            split2(f.z, f.w, hv.y, lv.y);
            const size_t o = (size_t)(z - 2) * WN + (size_t)i * 4;
            *reinterpret_cast<uint2*>(wvh + o) = hv;
            *reinterpret_cast<uint2*>(wvl + o) = lv;
        }
    }
}

// ---------------------------------------------------------------------------
// Q/K projection: single-pass fp16 GEMM.  grid (4,64,2), smem 27904 B.
// ---------------------------------------------------------------------------
__global__ __launch_bounds__(256) void gemm_qk_kernel(
    const __half* __restrict__ x16, const __half* __restrict__ w16,
    const float* __restrict__ bq, const float* __restrict__ bk,
    __half* __restrict__ q16, __half* __restrict__ k16)
{
    extern __shared__ char sm[];
    const int AH = 0, WH = 18432, SBIAS = 27648;
    const int z = blockIdx.z;
    const int n0 = blockIdx.x * 64, m0 = blockIdx.y * 128;
    const int tid = threadIdx.x, lane = tid & 31, wid = tid >> 5;
    const int wm = wid >> 1, wn = wid & 1;
    const int qr = lane >> 2, qc = lane & 3;
    const float* bias = z ? bk : bq;
    __half* C16 = z ? k16 : q16;

    if (tid < 16)
        *reinterpret_cast<float4*>(sm + SBIAS + tid * 16) =
            *reinterpret_cast<const float4*>(bias + n0 + tid * 4);

    const int arow = tid >> 1, ahalf = tid & 1;
    const __half* aS = x16 + (size_t)z * NSG + (size_t)(m0 + arow) * Gg + ahalf * 32;
    const unsigned aso = arow * 144 + ahalf * 64;
    const int wrow = tid >> 2, wq4 = tid & 3;
    const __half* wS = w16 + (size_t)z * WN + (size_t)(n0 + wrow) * Gg + wq4 * 16;
    const unsigned wso = wrow * 144 + wq4 * 32;

    const unsigned base = smem_u32(sm);
    const unsigned aoff = (wm * 32 + (lane & 15)) * 144 + ((lane >> 4) * 8) * 2;
    const unsigned boff = (wn * 32 + ((lane >> 4) & 1) * 8 + (lane & 7)) * 144
                        + (((lane >> 3) & 1) * 8) * 2;

    float acc[2][4][4] = {};
    uint4 ra[4], rw[2];
    #pragma unroll
    for (int u = 0; u < 4; u++) ra[u] = reinterpret_cast<const uint4*>(aS)[u];
    #pragma unroll
    for (int u = 0; u < 2; u++) rw[u] = reinterpret_cast<const uint4*>(wS)[u];

    for (int c = 0; c < 4; c++) {
        #pragma unroll
        for (int u = 0; u < 4; u++)
            *reinterpret_cast<uint4*>(sm + AH + aso + u * 16) = ra[u];
        #pragma unroll
        for (int u = 0; u < 2; u++)
            *reinterpret_cast<uint4*>(sm + WH + wso + u * 16) = rw[u];
        __syncthreads();

        if (c < 3) {
            const int go = (c + 1) * 64;
            #pragma unroll
            for (int u = 0; u < 4; u++) ra[u] = reinterpret_cast<const uint4*>(aS + go)[u];
            #pragma unroll
            for (int u = 0; u < 2; u++) rw[u] = reinterpret_cast<const uint4*>(wS + go)[u];
        }

        #pragma unroll
        for (int kk = 0; kk < 4; kk++) {
            unsigned fa[2][4], fb[2][4];
            #pragma unroll
            for (int mt = 0; mt < 2; mt++)
                ldsm4(fa[mt][0], fa[mt][1], fa[mt][2], fa[mt][3],
                      base + AH + aoff + mt * 2304 + kk * 32);
            #pragma unroll
            for (int g = 0; g < 2; g++)
                ldsm4(fb[g][0], fb[g][1], fb[g][2], fb[g][3],
                      base + WH + boff + g * 2304 + kk * 32);
            #pragma unroll
            for (int mt = 0; mt < 2; mt++)
                #pragma unroll
                for (int nt = 0; nt < 4; nt++)
                    mma_f16(acc[mt][nt], fa[mt], &fb[nt >> 1][(nt & 1) * 2]);
        }
        __syncthreads();
    }

    const float* bs = reinterpret_cast<const float*>(sm + SBIAS);
    __half* sh = reinterpret_cast<__half*>(sm);
    #pragma unroll
    for (int mt = 0; mt < 2; mt++) {
        const int r0 = wm * 32 + mt * 16 + qr;
        #pragma unroll
        for (int nt = 0; nt < 4; nt++) {
            const int col = wn * 32 + nt * 8 + qc * 2;
            #pragma unroll
            for (int pr = 0; pr < 2; pr++) {
                __half2 h2 = __floats2half2_rn(acc[mt][nt][pr * 2]     + bs[col],
                                               acc[mt][nt][pr * 2 + 1] + bs[col + 1]);
                *reinterpret_cast<__half2*>(sh + (r0 + pr * 8) * 72 + col) = h2;
            }
        }
    }
    __syncthreads();
    #pragma unroll
    for (int ps = 0; ps < 4; ps++) {
        const int idx = ps * 2048 + tid * 8;
        const int row = idx >> 6, col = idx & 63;
        uint4 hv = *reinterpret_cast<const uint4*>(sh + row * 72 + col);
        *reinterpret_cast<uint4*>(C16 + (size_t)(m0 + row) * Gg + n0 + col) = hv;
    }
}

// ---------------------------------------------------------------------------
// bf16x3 GEMM mainloop (V and out projections).
// ---------------------------------------------------------------------------
__device__ __forceinline__ void gemm_mainloop(
    char* sm, const __nv_bfloat16* Ahi, const __nv_bfloat16* Alo,
    const __nv_bfloat16* Whi, const __nv_bfloat16* Wlo,
    int m0, int n0, float acc[2][4][4])
{
    const int AH = 0, AL = 18432, WHo = 36864, WLo = 46080;
    const int tid = threadIdx.x, lane = tid & 31, wid = tid >> 5;
    const int wm = wid >> 1, wn = wid & 1;

    const int arow = tid >> 1, ahalf = tid & 1;
    const __nv_bfloat16* aH = Ahi + (size_t)(m0 + arow) * Gg + ahalf * 32;
    const __nv_bfloat16* aL = Alo + (size_t)(m0 + arow) * Gg + ahalf * 32;
    const unsigned aso = arow * 144 + ahalf * 64;
    const int wrow = tid >> 2, wq4 = tid & 3;
    const __nv_bfloat16* wH = Whi + (size_t)(n0 + wrow) * Gg + wq4 * 16;
    const __nv_bfloat16* wL = Wlo + (size_t)(n0 + wrow) * Gg + wq4 * 16;
    const unsigned wso = wrow * 144 + wq4 * 32;

    const unsigned base = smem_u32(sm);
    const unsigned aoff = (wm * 32 + (lane & 15)) * 144 + ((lane >> 4) * 8) * 2;
    const unsigned boff = (wn * 32 + ((lane >> 4) & 1) * 8 + (lane & 7)) * 144
                        + (((lane >> 3) & 1) * 8) * 2;

    uint4 rah[4], ral[4], rwh[2], rwl[2];
    #pragma unroll
    for (int u = 0; u < 4; u++) {
        rah[u] = reinterpret_cast<const uint4*>(aH)[u];
        ral[u] = reinterpret_cast<const uint4*>(aL)[u];
    }
    #pragma unroll
    for (int u = 0; u < 2; u++) {
        rwh[u] = reinterpret_cast<const uint4*>(wH)[u];
        rwl[u] = reinterpret_cast<const uint4*>(wL)[u];
    }

    for (int c = 0; c < 4; c++) {
        #pragma unroll
        for (int u = 0; u < 4; u++) {
            *reinterpret_cast<uint4*>(sm + AH + aso + u * 16) = rah[u];
            *reinterpret_cast<uint4*>(sm + AL + aso + u * 16) = ral[u];
        }
        #pragma unroll
        for (int u = 0; u < 2; u++) {
            *reinterpret_cast<uint4*>(sm + WHo + wso + u * 16) = rwh[u];
            *reinterpret_cast<uint4*>(sm + WLo + wso + u * 16) = rwl[u];
        }
        __syncthreads();

        if (c < 3) {
            const int go = (c + 1) * 64;
            #pragma unroll
            for (int u = 0; u < 4; u++) {
                rah[u] = reinterpret_cast<const uint4*>(aH + go)[u];
                ral[u] = reinterpret_cast<const uint4*>(aL + go)[u];
            }
            #pragma unroll
            for (int u = 0; u < 2; u++) {
                rwh[u] = reinterpret_cast<const uint4*>(wH + go)[u];
                rwl[u] = reinterpret_cast<const uint4*>(wL + go)[u];
            }
        }

        #pragma unroll
        for (int kk = 0; kk < 4; kk++) {
            unsigned fah[2][4], fal[2][4], fbh[2][4], fbl[2][4];
            #pragma unroll
            for (int mt = 0; mt < 2; mt++) {
                const unsigned ad = base + AH + aoff + mt * 2304 + kk * 32;
                ldsm4(fah[mt][0], fah[mt][1], fah[mt][2], fah[mt][3], ad);
                ldsm4(fal[mt][0], fal[mt][1], fal[mt][2], fal[mt][3], ad + (AL - AH));
            }
            #pragma unroll
            for (int g = 0; g < 2; g++) {
                const unsigned bd = base + WHo + boff + g * 2304 + kk * 32;
                ldsm4(fbh[g][0], fbh[g][1], fbh[g][2], fbh[g][3], bd);
                ldsm4(fbl[g][0], fbl[g][1], fbl[g][2], fbl[g][3], bd + (WLo - WHo));
            }
            #pragma unroll
            for (int mt = 0; mt < 2; mt++)
                #pragma unroll
                for (int nt = 0; nt < 4; nt++) {
                    const unsigned* pbh = &fbh[nt >> 1][(nt & 1) * 2];
                    const unsigned* pbl = &fbl[nt >> 1][(nt & 1) * 2];
                    mma_bf16(acc[mt][nt], fah[mt], pbh);
                    mma_bf16(acc[mt][nt], fah[mt], pbl);
                    mma_bf16(acc[mt][nt], fal[mt], pbh);
                }
        }
        __syncthreads();
    }
}

// bf16x3 projection, fp32 out (+bias).  2 CTAs/SM.
__global__ __launch_bounds__(256, 2) void gemm_out_kernel(
    const __nv_bfloat16* __restrict__ Ahi, const __nv_bfloat16* __restrict__ Alo,
    const __nv_bfloat16* __restrict__ Whi, const __nv_bfloat16* __restrict__ Wlo,
    const float* __restrict__ bias, float* __restrict__ C)
{
    extern __shared__ char sm[];
    const int SBIAS = 55296;
    const int n0 = blockIdx.x * 64, m0 = blockIdx.y * 128;
    const int tid = threadIdx.x, lane = tid & 31, wid = tid >> 5;
    const int wm = wid >> 1, wn = wid & 1;
    const int qr = lane >> 2, qc = lane & 3;

    if (tid < 16)
        *reinterpret_cast<float4*>(sm + SBIAS + tid * 16) =
            *reinterpret_cast<const float4*>(bias + n0 + tid * 4);

    float acc[2][4][4] = {};
    gemm_mainloop(sm, Ahi, Alo, Whi, Wlo, m0, n0, acc);

    const float* bs = reinterpret_cast<const float*>(sm + SBIAS);
    float* sc = reinterpret_cast<float*>(sm);
    #pragma unroll
    for (int mt = 0; mt < 2; mt++) {
        const int r0 = wm * 32 + mt * 16 + qr;
        #pragma unroll
        for (int nt = 0; nt < 4; nt++) {
            const int col = wn * 32 + nt * 8 + qc * 2;
            #pragma unroll
            for (int pr = 0; pr < 2; pr++) {
                float2 o = make_float2(acc[mt][nt][pr * 2]     + bs[col],
                                       acc[mt][nt][pr * 2 + 1] + bs[col + 1]);
                *reinterpret_cast<float2*>(sc + (r0 + pr * 8) * 68 + col) = o;
            }
        }
    }
    __syncthreads();
    #pragma unroll
    for (int ps = 0; ps < 8; ps++) {
        const int idx = ps * 1024 + tid * 4;
        const int row = idx >> 6, col = idx & 63;
        float4 vv = *reinterpret_cast<const float4*>(sc + row * 68 + col);
        *reinterpret_cast<float4*>(C + (size_t)(m0 + row) * Gg + n0 + col) = vv;
    }
}

// ---------------------------------------------------------------------------
// scores: P(fp16) = exp(scale*QK^T), two 64-row phases.  P stored DIRECTLY
// from fragments via intra-quad shuffles (no SMEM staging).
// grid (32,32,8), 256 thr, dyn smem 36864 B.
// ---------------------------------------------------------------------------
__global__ __launch_bounds__(256, 3) void scores_wm_kernel(
    const __half* __restrict__ Q, const __half* __restrict__ Kt,
    __half* __restrict__ P, float* __restrict__ part)
{
    extern __shared__ char sm[];
    const int QH = 0, KH = 18432;
    const int tid = threadIdx.x, lane = tid & 31, wid = tid >> 5;
    const int wm = wid >> 2, wn = wid & 3;
    const int bh = blockIdx.z, b = bh >> 2, h = bh & 3;
    const int i0 = blockIdx.y * 128, j0 = blockIdx.x * 128;

    {
        const int row = tid >> 1, half = tid & 1;
        const size_t qoff = ((size_t)(b * Ss + i0 + row)) * Gg + h * DKk + half * 32;
        const size_t koff = ((size_t)(b * Ss + j0 + row)) * Gg + h * DKk + half * 32;
        const unsigned so = row * 144 + half * 64;
        const uint4* q1 = reinterpret_cast<const uint4*>(Q + qoff);
        const uint4* k1 = reinterpret_cast<const uint4*>(Kt + koff);
        #pragma unroll
        for (int u = 0; u < 4; u++) {
            *reinterpret_cast<uint4*>(sm + QH + so + u * 16) = q1[u];
            *reinterpret_cast<uint4*>(sm + KH + so + u * 16) = k1[u];
        }
    }
    __syncthreads();

    const unsigned base = smem_u32(sm);
    const int qr = lane >> 2, qc = lane & 3;
    const unsigned boff = (wn * 32 + ((lane >> 4) & 1) * 8 + (lane & 7)) * 144
                        + (((lane >> 3) & 1) * 8) * 2;
    const int jbase = j0 + wn * 32;

    #pragma unroll
    for (int ph = 0; ph < 2; ph++) {
        const unsigned aoff = (ph * 64 + wm * 32 + (lane & 15)) * 144
                            + ((lane >> 4) * 8) * 2;
        float acc[2][4][4] = {};
        #pragma unroll
        for (int kk = 0; kk < 4; kk++) {
            unsigned aH[2][4], bH[2][4];
            #pragma unroll
            for (int mt = 0; mt < 2; mt++)
                ldsm4(aH[mt][0], aH[mt][1], aH[mt][2], aH[mt][3],
                      base + QH + aoff + mt * 2304 + kk * 32);
            #pragma unroll
            for (int g = 0; g < 2; g++)
                ldsm4(bH[g][0], bH[g][1], bH[g][2], bH[g][3],
                      base + KH + boff + g * 2304 + kk * 32);
            #pragma unroll
            for (int mt = 0; mt < 2; mt++)
                #pragma unroll
                for (int nt = 0; nt < 4; nt++)
                    mma_f16(acc[mt][nt], aH[mt], &bH[nt >> 1][(nt & 1) * 2]);
        }

        #pragma unroll
        for (int mt = 0; mt < 2; mt++)
            #pragma unroll
            for (int nt = 0; nt < 4; nt++)
                #pragma unroll
                for (int r = 0; r < 4; r++)
                    acc[mt][nt][r] = ex2f(acc[mt][nt][r] * EXP2K);

        // deterministic column partial sums over this warp's 32 rows
        #pragma unroll
        for (int nt = 0; nt < 4; nt++) {
            #pragma unroll
            for (int p = 0; p < 2; p++) {
                float s = 0.f;
                #pragma unroll
                for (int mt = 0; mt < 2; mt++) s += acc[mt][nt][p] + acc[mt][nt][p + 2];
                #pragma unroll
                for (int o = 4; o < 32; o <<= 1) s += __shfl_xor_sync(0xffffffffu, s, o);
                if (qr == 0)
                    part[((size_t)(bh * 32 + blockIdx.y) * 4 + ph * 2 + wm) * Ss
                         + jbase + nt * 8 + qc * 2 + p] = s;
            }
        }

        // direct coalesced P store via intra-quad shuffles:
        // lane (qr,qc) assembles cols [qc*8, qc*8+8) of its rows as one uint4.
        #pragma unroll
        for (int mt = 0; mt < 2; mt++) {
            #pragma unroll
            for (int pr = 0; pr < 2; pr++) {
                unsigned v[4];
                #pragma unroll
                for (int nt = 0; nt < 4; nt++) {
                    __half2 h2 = __floats2half2_rn(acc[mt][nt][pr * 2],
                                                   acc[mt][nt][pr * 2 + 1]);
                    v[nt] = *reinterpret_cast<unsigned*>(&h2);
                }
                unsigned w[4];
                #pragma unroll
                for (int r = 0; r < 4; r++) {
                    unsigned pub = v[(qc + r) & 3];
                    int srcq = (qc - r) & 3;
                    unsigned got = __shfl_sync(0xffffffffu, pub,
                                               (lane & 28) | srcq);
                    w[srcq] = got;
                }
                const int row = i0 + ph * 64 + wm * 32 + mt * 16 + pr * 8 + qr;
                const int col = jbase + qc * 8;
                *reinterpret_cast<uint4*>(P + ((size_t)bh * Ss + row) * Ss + col)
                    = make_uint4(w[0], w[1], w[2], w[3]);
            }
        }
    }
}

// ---------------------------------------------------------------------------
// Fused colsum + V scale/transpose.  grid (64,8) x 256
// ---------------------------------------------------------------------------
__global__ __launch_bounds__(256) void scale_v_t_kernel(
    const float* __restrict__ v, const float* __restrict__ part,
    __half* __restrict__ tH)
{
    __shared__ float ts[64][65];
    __shared__ float wsum[4][64];
    __shared__ float winv_s[64];
    const int tid = threadIdx.x, bh = blockIdx.y, b = bh >> 2, h = bh & 3;
    const int j0 = blockIdx.x * 64;

    {
        const int j = tid & 63, cq = tid >> 6;
        const float* p = part + (size_t)bh * 128 * Ss + (size_t)cq * 32 * Ss + j0 + j;
        float s = 0.f;
        #pragma unroll
        for (int c = 0; c < 32; c++) s += p[(size_t)c * Ss];
        wsum[cq][j] = s;
    }
    {
        const int j = tid >> 2, c0 = (tid & 3) * 16;
        const float* src = v + ((size_t)(b * Ss + j0 + j)) * Gg + h * DKk + c0;
        #pragma unroll
        for (int u = 0; u < 4; u++) {
            float4 f = *reinterpret_cast<const float4*>(src + u * 4);
            ts[j][c0 + 4*u]     = f.x; ts[j][c0 + 4*u + 1] = f.y;
            ts[j][c0 + 4*u + 2] = f.z; ts[j][c0 + 4*u + 3] = f.w;
        }
    }
    __syncthreads();
    if (tid < 64)
        winv_s[tid] = 1.0f / (((wsum[0][tid] + wsum[1][tid])
                             + (wsum[2][tid] + wsum[3][tid])));
    __syncthreads();

    const int d = tid >> 2, jj0 = (tid & 3) * 16;
    const size_t ob = (((size_t)bh) * DKk + d) * Ss + j0 + jj0;
    __half hbuf[16];
    #pragma unroll
    for (int u = 0; u < 16; u++)
        hbuf[u] = __float2half_rn(ts[jj0 + u][d] * winv_s[jj0 + u] * VSCALE);
    #pragma unroll
    for (int u = 0; u < 2; u++)
        *reinterpret_cast<uint4*>(tH + ob + u * 8) = reinterpret_cast<uint4*>(hbuf)[u];
}

// ---------------------------------------------------------------------------
// pv: Att = (P @ Vw^T)/4096, single fp16 MMA pass, 128x64 CTA tile.
// grid (32,8), 256 thr, smem 36864 B.
// ---------------------------------------------------------------------------
__global__ __launch_bounds__(256) void pv_wm_kernel(
    const __half* __restrict__ P, const __half* __restrict__ vt,
    __nv_bfloat16* __restrict__ atth, __nv_bfloat16* __restrict__ attl)
{
    extern __shared__ char sm[];
    const int PH = 0, VH = 18432;
    const int tid = threadIdx.x, lane = tid & 31, wid = tid >> 5;
    const int wm = wid >> 1, wn = wid & 1;
    const int bh = blockIdx.y, b = bh >> 2, h = bh & 3;
    const int i0 = blockIdx.x * 128;
    const int qr = lane >> 2, qc = lane & 3;

    const int prow = tid >> 1, phalf = tid & 1;
    const __half* pS = P + ((size_t)bh * Ss + i0 + prow) * Ss + phalf * 32;
    const unsigned pso = prow * 144 + phalf * 64;
    const int vrow = tid >> 2, vq = tid & 3;
    const __half* vS = vt + ((size_t)bh * DKk + vrow) * Ss + vq * 16;
    const unsigned vso = VH + vrow * 144 + vq * 32;

    const unsigned base = smem_u32(sm);
    const unsigned aoff = (wm * 32 + (lane & 15)) * 144 + ((lane >> 4) * 8) * 2;
    const unsigned boff = (wn * 32 + ((lane >> 4) & 1) * 8 + (lane & 7)) * 144
                        + (((lane >> 3) & 1) * 8) * 2;

    float acc[2][4][4] = {};
    uint4 rp[4], rv[2];

    #pragma unroll
    for (int u = 0; u < 4; u++) rp[u] = reinterpret_cast<const uint4*>(pS)[u];
    rv[0] = reinterpret_cast<const uint4*>(vS)[0];
    rv[1] = reinterpret_cast<const uint4*>(vS)[1];

    for (int c = 0; c < 64; c++) {
        #pragma unroll
        for (int u = 0; u < 4; u++)
            *reinterpret_cast<uint4*>(sm + PH + pso + u * 16) = rp[u];
        *reinterpret_cast<uint4*>(sm + vso)      = rv[0];
        *reinterpret_cast<uint4*>(sm + vso + 16) = rv[1];
        __syncthreads();

        if (c < 63) {
            const size_t go = (size_t)(c + 1) * 64;
            #pragma unroll
            for (int u = 0; u < 4; u++)
                rp[u] = reinterpret_cast<const uint4*>(pS + go)[u];
            rv[0] = reinterpret_cast<const uint4*>(vS + go)[0];
            rv[1] = reinterpret_cast<const uint4*>(vS + go)[1];
        }

        #pragma unroll
        for (int kk = 0; kk < 4; kk++) {
            unsigned aH[2][4], bH[2][4];
            #pragma unroll
            for (int mt = 0; mt < 2; mt++) {
                const unsigned ad = base + PH + aoff + mt * 2304 + kk * 32;
                ldsm4(aH[mt][0], aH[mt][1], aH[mt][2], aH[mt][3], ad);
            }
            #pragma unroll
            for (int g = 0; g < 2; g++) {
                const unsigned bd = base + VH + boff + g * 2304 + kk * 32;
                ldsm4(bH[g][0], bH[g][1], bH[g][2], bH[g][3], bd);
            }
            #pragma unroll
            for (int mt = 0; mt < 2; mt++)
                #pragma unroll
                for (int nt = 0; nt < 4; nt++)
                    mma_f16(acc[mt][nt], aH[mt], &bH[nt >> 1][(nt & 1) * 2]);
        }
        __syncthreads();
    }

    __nv_bfloat16* sh = reinterpret_cast<__nv_bfloat16*>(sm);            // stride 72
    __nv_bfloat16* sl = reinterpret_cast<__nv_bfloat16*>(sm + 18432);
    #pragma unroll
    for (int mt = 0; mt < 2; mt++) {
        const int r0 = wm * 32 + mt * 16 + qr;
        #pragma unroll
        for (int nt = 0; nt < 4; nt++) {
            const int col = wn * 32 + nt * 8 + qc * 2;
            #pragma unroll
            for (int pr = 0; pr < 2; pr++) {
                unsigned hv, lv;
                split2(acc[mt][nt][pr * 2] * OSCALE,
                       acc[mt][nt][pr * 2 + 1] * OSCALE, hv, lv);
                *reinterpret_cast<unsigned*>(sh + (r0 + pr * 8) * 72 + col) = hv;
                *reinterpret_cast<unsigned*>(sl + (r0 + pr * 8) * 72 + col) = lv;
            }
        }
    }
    __syncthreads();
    #pragma unroll
    for (int ps = 0; ps < 4; ps++) {
        const int idx = ps * 2048 + tid * 8;
        const int row = idx >> 6, col = idx & 63;
        uint4 hv = *reinterpret_cast<const uint4*>(sh + row * 72 + col);
        uint4 lv = *reinterpret_cast<const uint4*>(sl + row * 72 + col);
        const size_t o = ((size_t)(b * Ss + i0 + row)) * Gg + h * DKk + col;
        *reinterpret_cast<uint4*>(atth + o) = hv;
        *reinterpret_cast<uint4*>(attl + o) = lv;
    }
}

// ---------------------------------------------------------------------------
extern "C" void kernel_launch(void* const* d_in, const int* in_sizes, int n_in,
                              void* d_out, int out_size)
{
    const float* x  = (const float*)d_in[0];
    const float* wq = (const float*)d_in[1];
    const float* bq = (const float*)d_in[2];
    const float* wk = (const float*)d_in[3];
    const float* bk = (const float*)d_in[4];
    const float* wv = (const float*)d_in[5];
    const float* bv = (const float*)d_in[6];
    const float* wo = (const float*)d_in[7];
    const float* bo = (const float*)d_in[8];
    float* out = (float*)d_out;

    __half *x16, *w16, *q16, *k16, *p, *vt;
    __nv_bfloat16 *xvh, *xvl, *wvh, *wvl, *atth, *attl;
    float *v, *part;
    cudaGetSymbolAddress((void**)&x16, g_x16);
    cudaGetSymbolAddress((void**)&xvh, g_xvh);  cudaGetSymbolAddress((void**)&xvl, g_xvl);
    cudaGetSymbolAddress((void**)&w16, g_w16);
    cudaGetSymbolAddress((void**)&wvh, g_wvh);  cudaGetSymbolAddress((void**)&wvl, g_wvl);
    cudaGetSymbolAddress((void**)&q16, g_q16);  cudaGetSymbolAddress((void**)&k16, g_k16);
    cudaGetSymbolAddress((void**)&v,   g_v);
    cudaGetSymbolAddress((void**)&p,   g_p);
    cudaGetSymbolAddress((void**)&part,g_part);
    cudaGetSymbolAddress((void**)&vt,  g_vt);
    cudaGetSymbolAddress((void**)&atth,g_atth); cudaGetSymbolAddress((void**)&attl,g_attl);

    const int SC_SMEM = 36864;
    const int PV_SMEM = 36864;
    const int TC_SMEM = 55552;
    const int QK_SMEM = 27904;
    cudaFuncSetAttribute(scores_wm_kernel, cudaFuncAttributeMaxDynamicSharedMemorySize, SC_SMEM);
    cudaFuncSetAttribute(pv_wm_kernel,     cudaFuncAttributeMaxDynamicSharedMemorySize, PV_SMEM);
    cudaFuncSetAttribute(gemm_qk_kernel,   cudaFuncAttributeMaxDynamicSharedMemorySize, QK_SMEM);
    cudaFuncSetAttribute(gemm_out_kernel,  cudaFuncAttributeMaxDynamicSharedMemorySize, TC_SMEM);

    // fused splits
    split_all_kernel<<<6400, 256>>>(x, wq, wk, wv, wo,
                                    x16, xvh, xvl, w16, wvh, wvl);

    // projections
    gemm_qk_kernel<<<dim3(4, 64, 2), 256, QK_SMEM>>>(x16, w16, bq, bk, q16, k16);
    gemm_out_kernel<<<dim3(4, 64), 256, TC_SMEM>>>(xvh, xvl, wvh, wvl, bv, v);

    // attention
    scores_wm_kernel<<<dim3(32, 32, 8), 256, SC_SMEM>>>(q16, k16, p, part);
    scale_v_t_kernel<<<dim3(64, 8), 256>>>(v, part, vt);
    pv_wm_kernel<<<dim3(32, 8), 256, PV_SMEM>>>(p, vt, atth, attl);

    // out projection
    gemm_out_kernel<<<dim3(4, 64), 256, TC_SMEM>>>(atth, attl,
        wvh + WN, wvl + WN, bo, out);
}

// round 17
// speedup vs baseline: 1.1364x; 1.1364x over previous
#include <cuda_runtime.h>
#include <cuda_bf16.h>
#include <cuda_fp16.h>
#include <math.h>

#define Bb   2
#define Ss   4096
#define Gg   256
#define Hh   4
#define DKk  64
#define DIMd 768
#define EXP2K (0.125f * 1.44269504088896341f)
#define VSCALE 4096.0f
#define OSCALE (1.0f / 4096.0f)
#define NSG (Bb * Ss * Gg)
#define WN (Gg * Gg)

// ---------------- scratch ----------------
__device__ __half         g_x16[2 * NSG];
__device__ __nv_bfloat16  g_xvh[NSG];
__device__ __nv_bfloat16  g_xvl[NSG];
__device__ __half         g_w16[2 * WN];
__device__ __nv_bfloat16  g_wvh[2 * WN];
__device__ __nv_bfloat16  g_wvl[2 * WN];
__device__ __half g_q16[NSG];
__device__ __half g_k16[NSG];
__device__ float  g_v  [NSG];
__device__ __half g_p[(size_t)Bb * Hh * Ss * Ss];
__device__ float g_part[(size_t)Bb * Hh * 128 * Ss];
__device__ __half g_vt[Bb * Hh * DKk * Ss];
__device__ __nv_bfloat16 g_atth[NSG];
__device__ __nv_bfloat16 g_attl[NSG];

// ---------------- helpers ----------------
__device__ __forceinline__ unsigned smem_u32(const void* p) {
    unsigned a;
    asm("{ .reg .u64 t; cvta.to.shared.u64 t, %1; cvt.u32.u64 %0, t; }" : "=r"(a) : "l"(p));
    return a;
}
__device__ __forceinline__ float ex2f(float x) {
    float r;
    asm("ex2.approx.ftz.f32 %0, %1;" : "=f"(r) : "f"(x));
    return r;
}
__device__ __forceinline__ void ldsm4(unsigned& r0, unsigned& r1, unsigned& r2,
                                      unsigned& r3, unsigned addr) {
    asm volatile("ldmatrix.sync.aligned.m8n8.x4.shared.b16 {%0,%1,%2,%3}, [%4];"
                 : "=r"(r0), "=r"(r1), "=r"(r2), "=r"(r3) : "r"(addr));
}
__device__ __forceinline__ void mma_bf16(float* c, const unsigned* a, const unsigned* b) {
    asm volatile(
        "mma.sync.aligned.m16n8k16.row.col.f32.bf16.bf16.f32 "
        "{%0,%1,%2,%3},{%4,%5,%6,%7},{%8,%9},{%0,%1,%2,%3};"
        : "+f"(c[0]), "+f"(c[1]), "+f"(c[2]), "+f"(c[3])
        : "r"(a[0]), "r"(a[1]), "r"(a[2]), "r"(a[3]), "r"(b[0]), "r"(b[1]));
}
__device__ __forceinline__ void mma_f16(float* c, const unsigned* a, const unsigned* b) {
    asm volatile(
        "mma.sync.aligned.m16n8k16.row.col.f32.f16.f16.f32 "
        "{%0,%1,%2,%3},{%4,%5,%6,%7},{%8,%9},{%0,%1,%2,%3};"
        : "+f"(c[0]), "+f"(c[1]), "+f"(c[2]), "+f"(c[3])
        : "r"(a[0]), "r"(a[1]), "r"(a[2]), "r"(a[3]), "r"(b[0]), "r"(b[1]));
}
__device__ __forceinline__ void split2(float a, float b, unsigned& h, unsigned& l) {
    __nv_bfloat162 h2 = __floats2bfloat162_rn(a, b);
    __nv_bfloat162 l2 = __floats2bfloat162_rn(a - __bfloat162float(h2.x),
                                              b - __bfloat162float(h2.y));
    h = *reinterpret_cast<unsigned*>(&h2);
    l = *reinterpret_cast<unsigned*>(&l2);
}

// ---------------- fused split kernel ----------------
__global__ __launch_bounds__(256) void split_all_kernel(
    const float* __restrict__ x,
    const float* __restrict__ w0, const float* __restrict__ w1,
    const float* __restrict__ w2, const float* __restrict__ w3,
    __half* __restrict__ x16,
    __nv_bfloat16* __restrict__ xvh, __nv_bfloat16* __restrict__ xvl,
    __half* __restrict__ w16,
    __nv_bfloat16* __restrict__ wvh, __nv_bfloat16* __restrict__ wvl)
{
    if (blockIdx.x < 6144) {
        const int i = blockIdx.x * 256 + threadIdx.x;
        float4 f = reinterpret_cast<const float4*>(x)[i];
        const int row = i / 192, c4 = i - row * 192;
        const int slice = c4 >> 6, w4 = c4 & 63;
        if (slice < 2) {
            const size_t o = (size_t)slice * NSG + (size_t)row * Gg + w4 * 4;
            uint2 hv;
            __half2 a = __floats2half2_rn(f.x, f.y);
            __half2 b2 = __floats2half2_rn(f.z, f.w);
            hv.x = *reinterpret_cast<unsigned*>(&a);
            hv.y = *reinterpret_cast<unsigned*>(&b2);
            *reinterpret_cast<uint2*>(x16 + o) = hv;
        } else {
            const size_t o = (size_t)row * Gg + w4 * 4;
            uint2 hv, lv;
            split2(f.x, f.y, hv.x, lv.x);
            split2(f.z, f.w, hv.y, lv.y);
            *reinterpret_cast<uint2*>(xvh + o) = hv;
            *reinterpret_cast<uint2*>(xvl + o) = lv;
        }
    } else {
        const int bi = blockIdx.x - 6144;
        const int z = bi >> 6;
        const int i = (bi & 63) * 256 + threadIdx.x;
        const float* src = (z == 0) ? w0 : (z == 1) ? w1 : (z == 2) ? w2 : w3;
        float4 f = reinterpret_cast<const float4*>(src)[i];
        if (z < 2) {
            uint2 hv;
            __half2 a = __floats2half2_rn(f.x, f.y);
            __half2 b2 = __floats2half2_rn(f.z, f.w);
            hv.x = *reinterpret_cast<unsigned*>(&a);
            hv.y = *reinterpret_cast<unsigned*>(&b2);
            *reinterpret_cast<uint2*>(w16 + (size_t)z * WN + (size_t)i * 4) = hv;
        } else {
            uint2 hv, lv;
            split2(f.x, f.y, hv.x, lv.x);
            split2(f.z, f.w, hv.y, lv.y);
            const size_t o = (size_t)(z - 2) * WN + (size_t)i * 4;
            *reinterpret_cast<uint2*>(wvh + o) = hv;
            *reinterpret_cast<uint2*>(wvl + o) = lv;
        }
    }
}

// ---------------------------------------------------------------------------
// Q/K projection: single-pass fp16 GEMM.  grid (4,64,2), smem 27904 B.
// ---------------------------------------------------------------------------
__global__ __launch_bounds__(256) void gemm_qk_kernel(
    const __half* __restrict__ x16, const __half* __restrict__ w16,
    const float* __restrict__ bq, const float* __restrict__ bk,
    __half* __restrict__ q16, __half* __restrict__ k16)
{
    extern __shared__ char sm[];
    const int AH = 0, WH = 18432, SBIAS = 27648;
    const int z = blockIdx.z;
    const int n0 = blockIdx.x * 64, m0 = blockIdx.y * 128;
    const int tid = threadIdx.x, lane = tid & 31, wid = tid >> 5;
    const int wm = wid >> 1, wn = wid & 1;
    const int qr = lane >> 2, qc = lane & 3;
    const float* bias = z ? bk : bq;
    __half* C16 = z ? k16 : q16;

    if (tid < 16)
        *reinterpret_cast<float4*>(sm + SBIAS + tid * 16) =
            *reinterpret_cast<const float4*>(bias + n0 + tid * 4);

    const int arow = tid >> 1, ahalf = tid & 1;
    const __half* aS = x16 + (size_t)z * NSG + (size_t)(m0 + arow) * Gg + ahalf * 32;
    const unsigned aso = arow * 144 + ahalf * 64;
    const int wrow = tid >> 2, wq4 = tid & 3;
    const __half* wS = w16 + (size_t)z * WN + (size_t)(n0 + wrow) * Gg + wq4 * 16;
    const unsigned wso = wrow * 144 + wq4 * 32;

    const unsigned base = smem_u32(sm);
    const unsigned aoff = (wm * 32 + (lane & 15)) * 144 + ((lane >> 4) * 8) * 2;
    const unsigned boff = (wn * 32 + ((lane >> 4) & 1) * 8 + (lane & 7)) * 144
                        + (((lane >> 3) & 1) * 8) * 2;

    float acc[2][4][4] = {};
    uint4 ra[4], rw[2];
    #pragma unroll
    for (int u = 0; u < 4; u++) ra[u] = reinterpret_cast<const uint4*>(aS)[u];
    #pragma unroll
    for (int u = 0; u < 2; u++) rw[u] = reinterpret_cast<const uint4*>(wS)[u];

    for (int c = 0; c < 4; c++) {
        #pragma unroll
        for (int u = 0; u < 4; u++)
            *reinterpret_cast<uint4*>(sm + AH + aso + u * 16) = ra[u];
        #pragma unroll
        for (int u = 0; u < 2; u++)
            *reinterpret_cast<uint4*>(sm + WH + wso + u * 16) = rw[u];
        __syncthreads();

        if (c < 3) {
            const int go = (c + 1) * 64;
            #pragma unroll
            for (int u = 0; u < 4; u++) ra[u] = reinterpret_cast<const uint4*>(aS + go)[u];
            #pragma unroll
            for (int u = 0; u < 2; u++) rw[u] = reinterpret_cast<const uint4*>(wS + go)[u];
        }

        #pragma unroll
        for (int kk = 0; kk < 4; kk++) {
            unsigned fa[2][4], fb[2][4];
            #pragma unroll
            for (int mt = 0; mt < 2; mt++)
                ldsm4(fa[mt][0], fa[mt][1], fa[mt][2], fa[mt][3],
                      base + AH + aoff + mt * 2304 + kk * 32);
            #pragma unroll
            for (int g = 0; g < 2; g++)
                ldsm4(fb[g][0], fb[g][1], fb[g][2], fb[g][3],
                      base + WH + boff + g * 2304 + kk * 32);
            #pragma unroll
            for (int mt = 0; mt < 2; mt++)
                #pragma unroll
                for (int nt = 0; nt < 4; nt++)
                    mma_f16(acc[mt][nt], fa[mt], &fb[nt >> 1][(nt & 1) * 2]);
        }
        __syncthreads();
    }

    const float* bs = reinterpret_cast<const float*>(sm + SBIAS);
    __half* sh = reinterpret_cast<__half*>(sm);
    #pragma unroll
    for (int mt = 0; mt < 2; mt++) {
        const int r0 = wm * 32 + mt * 16 + qr;
        #pragma unroll
        for (int nt = 0; nt < 4; nt++) {
            const int col = wn * 32 + nt * 8 + qc * 2;
            #pragma unroll
            for (int pr = 0; pr < 2; pr++) {
                __half2 h2 = __floats2half2_rn(acc[mt][nt][pr * 2]     + bs[col],
                                               acc[mt][nt][pr * 2 + 1] + bs[col + 1]);
                *reinterpret_cast<__half2*>(sh + (r0 + pr * 8) * 72 + col) = h2;
            }
        }
    }
    __syncthreads();
    #pragma unroll
    for (int ps = 0; ps < 4; ps++) {
        const int idx = ps * 2048 + tid * 8;
        const int row = idx >> 6, col = idx & 63;
        uint4 hv = *reinterpret_cast<const uint4*>(sh + row * 72 + col);
        *reinterpret_cast<uint4*>(C16 + (size_t)(m0 + row) * Gg + n0 + col) = hv;
    }
}

// ---------------------------------------------------------------------------
// bf16x3 GEMM mainloop (V and out projections).
// ---------------------------------------------------------------------------
__device__ __forceinline__ void gemm_mainloop(
    char* sm, const __nv_bfloat16* Ahi, const __nv_bfloat16* Alo,
    const __nv_bfloat16* Whi, const __nv_bfloat16* Wlo,
    int m0, int n0, float acc[2][4][4])
{
    const int AH = 0, AL = 18432, WHo = 36864, WLo = 46080;
    const int tid = threadIdx.x, lane = tid & 31, wid = tid >> 5;
    const int wm = wid >> 1, wn = wid & 1;

    const int arow = tid >> 1, ahalf = tid & 1;
    const __nv_bfloat16* aH = Ahi + (size_t)(m0 + arow) * Gg + ahalf * 32;
    const __nv_bfloat16* aL = Alo + (size_t)(m0 + arow) * Gg + ahalf * 32;
    const unsigned aso = arow * 144 + ahalf * 64;
    const int wrow = tid >> 2, wq4 = tid & 3;
    const __nv_bfloat16* wH = Whi + (size_t)(n0 + wrow) * Gg + wq4 * 16;
    const __nv_bfloat16* wL = Wlo + (size_t)(n0 + wrow) * Gg + wq4 * 16;
    const unsigned wso = wrow * 144 + wq4 * 32;

    const unsigned base = smem_u32(sm);
    const unsigned aoff = (wm * 32 + (lane & 15)) * 144 + ((lane >> 4) * 8) * 2;
    const unsigned boff = (wn * 32 + ((lane >> 4) & 1) * 8 + (lane & 7)) * 144
                        + (((lane >> 3) & 1) * 8) * 2;

    uint4 rah[4], ral[4], rwh[2], rwl[2];
    #pragma unroll
    for (int u = 0; u < 4; u++) {
        rah[u] = reinterpret_cast<const uint4*>(aH)[u];
        ral[u] = reinterpret_cast<const uint4*>(aL)[u];
    }
    #pragma unroll
    for (int u = 0; u < 2; u++) {
        rwh[u] = reinterpret_cast<const uint4*>(wH)[u];
        rwl[u] = reinterpret_cast<const uint4*>(wL)[u];
    }

    for (int c = 0; c < 4; c++) {
        #pragma unroll
        for (int u = 0; u < 4; u++) {
            *reinterpret_cast<uint4*>(sm + AH + aso + u * 16) = rah[u];
            *reinterpret_cast<uint4*>(sm + AL + aso + u * 16) = ral[u];
        }
        #pragma unroll
        for (int u = 0; u < 2; u++) {
            *reinterpret_cast<uint4*>(sm + WHo + wso + u * 16) = rwh[u];
            *reinterpret_cast<uint4*>(sm + WLo + wso + u * 16) = rwl[u];
        }
        __syncthreads();

        if (c < 3) {
            const int go = (c + 1) * 64;
            #pragma unroll
            for (int u = 0; u < 4; u++) {
                rah[u] = reinterpret_cast<const uint4*>(aH + go)[u];
                ral[u] = reinterpret_cast<const uint4*>(aL + go)[u];
            }
            #pragma unroll
            for (int u = 0; u < 2; u++) {
                rwh[u] = reinterpret_cast<const uint4*>(wH + go)[u];
                rwl[u] = reinterpret_cast<const uint4*>(wL + go)[u];
            }
        }

        #pragma unroll
        for (int kk = 0; kk < 4; kk++) {
            unsigned fah[2][4], fal[2][4], fbh[2][4], fbl[2][4];
            #pragma unroll
            for (int mt = 0; mt < 2; mt++) {
                const unsigned ad = base + AH + aoff + mt * 2304 + kk * 32;
                ldsm4(fah[mt][0], fah[mt][1], fah[mt][2], fah[mt][3], ad);
                ldsm4(fal[mt][0], fal[mt][1], fal[mt][2], fal[mt][3], ad + (AL - AH));
            }
            #pragma unroll
            for (int g = 0; g < 2; g++) {
                const unsigned bd = base + WHo + boff + g * 2304 + kk * 32;
                ldsm4(fbh[g][0], fbh[g][1], fbh[g][2], fbh[g][3], bd);
                ldsm4(fbl[g][0], fbl[g][1], fbl[g][2], fbl[g][3], bd + (WLo - WHo));
            }
            #pragma unroll
            for (int mt = 0; mt < 2; mt++)
                #pragma unroll
                for (int nt = 0; nt < 4; nt++) {
                    const unsigned* pbh = &fbh[nt >> 1][(nt & 1) * 2];
                    const unsigned* pbl = &fbl[nt >> 1][(nt & 1) * 2];
                    mma_bf16(acc[mt][nt], fah[mt], pbh);
                    mma_bf16(acc[mt][nt], fah[mt], pbl);
                    mma_bf16(acc[mt][nt], fal[mt], pbh);
                }
        }
        __syncthreads();
    }
}

// bf16x3 projection, fp32 out (+bias).  2 CTAs/SM.
__global__ __launch_bounds__(256, 2) void gemm_out_kernel(
    const __nv_bfloat16* __restrict__ Ahi, const __nv_bfloat16* __restrict__ Alo,
    const __nv_bfloat16* __restrict__ Whi, const __nv_bfloat16* __restrict__ Wlo,
    const float* __restrict__ bias, float* __restrict__ C)
{
    extern __shared__ char sm[];
    const int SBIAS = 55296;
    const int n0 = blockIdx.x * 64, m0 = blockIdx.y * 128;
    const int tid = threadIdx.x, lane = tid & 31, wid = tid >> 5;
    const int wm = wid >> 1, wn = wid & 1;
    const int qr = lane >> 2, qc = lane & 3;

    if (tid < 16)
        *reinterpret_cast<float4*>(sm + SBIAS + tid * 16) =
            *reinterpret_cast<const float4*>(bias + n0 + tid * 4);

    float acc[2][4][4] = {};
    gemm_mainloop(sm, Ahi, Alo, Whi, Wlo, m0, n0, acc);

    const float* bs = reinterpret_cast<const float*>(sm + SBIAS);
    float* sc = reinterpret_cast<float*>(sm);
    #pragma unroll
    for (int mt = 0; mt < 2; mt++) {
        const int r0 = wm * 32 + mt * 16 + qr;
        #pragma unroll
        for (int nt = 0; nt < 4; nt++) {
            const int col = wn * 32 + nt * 8 + qc * 2;
            #pragma unroll
            for (int pr = 0; pr < 2; pr++) {
                float2 o = make_float2(acc[mt][nt][pr * 2]     + bs[col],
                                       acc[mt][nt][pr * 2 + 1] + bs[col + 1]);
                *reinterpret_cast<float2*>(sc + (r0 + pr * 8) * 68 + col) = o;
            }
        }
    }
    __syncthreads();
    #pragma unroll
    for (int ps = 0; ps < 8; ps++) {
        const int idx = ps * 1024 + tid * 4;
        const int row = idx >> 6, col = idx & 63;
        float4 vv = *reinterpret_cast<const float4*>(sc + row * 68 + col);
        *reinterpret_cast<float4*>(C + (size_t)(m0 + row) * Gg + n0 + col) = vv;
    }
}

// ---------------------------------------------------------------------------
// scores: P(fp16) = exp(scale*QK^T), two 64-row phases, SMEM-staged coalesced
// P store (R15).  NEW: K-side B fragments hoisted out of the phase loop
// (loaded once, reused by both phases) -> 25% fewer LDSM.
// grid (32,32,8), 256 thr, dyn smem 54272 B, 2 CTAs/SM.
// ---------------------------------------------------------------------------
__global__ __launch_bounds__(256, 2) void scores_wm_kernel(
    const __half* __restrict__ Q, const __half* __restrict__ Kt,
    __half* __restrict__ P, float* __restrict__ part)
{
    extern __shared__ char sm[];
    const int QH = 0, KH = 18432, STG = 36864;
    const int tid = threadIdx.x, lane = tid & 31, wid = tid >> 5;
    const int wm = wid >> 2, wn = wid & 3;
    const int bh = blockIdx.z, b = bh >> 2, h = bh & 3;
    const int i0 = blockIdx.y * 128, j0 = blockIdx.x * 128;

    {
        const int row = tid >> 1, half = tid & 1;
        const size_t qoff = ((size_t)(b * Ss + i0 + row)) * Gg + h * DKk + half * 32;
        const size_t koff = ((size_t)(b * Ss + j0 + row)) * Gg + h * DKk + half * 32;
        const unsigned so = row * 144 + half * 64;
        const uint4* q1 = reinterpret_cast<const uint4*>(Q + qoff);
        const uint4* k1 = reinterpret_cast<const uint4*>(Kt + koff);
        #pragma unroll
        for (int u = 0; u < 4; u++) {
            *reinterpret_cast<uint4*>(sm + QH + so + u * 16) = q1[u];
            *reinterpret_cast<uint4*>(sm + KH + so + u * 16) = k1[u];
        }
    }
    __syncthreads();

    const unsigned base = smem_u32(sm);
    const int qr = lane >> 2, qc = lane & 3;
    const unsigned boff = (wn * 32 + ((lane >> 4) & 1) * 8 + (lane & 7)) * 144
                        + (((lane >> 3) & 1) * 8) * 2;
    const int jbase = j0 + wn * 32;
    __half* stg = reinterpret_cast<__half*>(sm + STG);

    // hoisted B fragments: identical across both phases
    unsigned bF[4][2][4];
    #pragma unroll
    for (int kk = 0; kk < 4; kk++)
        #pragma unroll
        for (int g = 0; g < 2; g++)
            ldsm4(bF[kk][g][0], bF[kk][g][1], bF[kk][g][2], bF[kk][g][3],
                  base + KH + boff + g * 2304 + kk * 32);

    #pragma unroll
    for (int ph = 0; ph < 2; ph++) {
        const unsigned aoff = (ph * 64 + wm * 32 + (lane & 15)) * 144
                            + ((lane >> 4) * 8) * 2;
        float acc[2][4][4] = {};
        #pragma unroll
        for (int kk = 0; kk < 4; kk++) {
            unsigned aH[2][4];
            #pragma unroll
            for (int mt = 0; mt < 2; mt++)
                ldsm4(aH[mt][0], aH[mt][1], aH[mt][2], aH[mt][3],
                      base + QH + aoff + mt * 2304 + kk * 32);
            #pragma unroll
            for (int mt = 0; mt < 2; mt++)
                #pragma unroll
                for (int nt = 0; nt < 4; nt++)
                    mma_f16(acc[mt][nt], aH[mt], &bF[kk][nt >> 1][(nt & 1) * 2]);
        }

        #pragma unroll
        for (int mt = 0; mt < 2; mt++)
            #pragma unroll
            for (int nt = 0; nt < 4; nt++)
                #pragma unroll
                for (int r = 0; r < 4; r++)
                    acc[mt][nt][r] = ex2f(acc[mt][nt][r] * EXP2K);

        // deterministic column partial sums over this warp's 32 rows
        #pragma unroll
        for (int nt = 0; nt < 4; nt++) {
            #pragma unroll
            for (int p = 0; p < 2; p++) {
                float s = 0.f;
                #pragma unroll
                for (int mt = 0; mt < 2; mt++) s += acc[mt][nt][p] + acc[mt][nt][p + 2];
                #pragma unroll
                for (int o = 4; o < 32; o <<= 1) s += __shfl_xor_sync(0xffffffffu, s, o);
                if (qr == 0)
                    part[((size_t)(bh * 32 + blockIdx.y) * 4 + ph * 2 + wm) * Ss
                         + jbase + nt * 8 + qc * 2 + p] = s;
            }
        }

        __syncthreads();     // prior phase's staging reads complete
        #pragma unroll
        for (int mt = 0; mt < 2; mt++) {
            const int r0 = wm * 32 + mt * 16 + qr;
            #pragma unroll
            for (int nt = 0; nt < 4; nt++) {
                const int col = wn * 32 + nt * 8 + qc * 2;
                #pragma unroll
                for (int pr = 0; pr < 2; pr++) {
                    __half2 h2 = __floats2half2_rn(acc[mt][nt][pr * 2],
                                                   acc[mt][nt][pr * 2 + 1]);
                    *reinterpret_cast<__half2*>(stg + (r0 + pr * 8) * 136 + col) = h2;
                }
            }
        }
        __syncthreads();
        {
            const size_t pb = ((size_t)bh * Ss + i0 + ph * 64) * Ss + j0;
            #pragma unroll
            for (int ps = 0; ps < 4; ps++) {
                const int el = ps * 2048 + tid * 8;
                const int row = el >> 7, col = el & 127;
                uint4 vv = *reinterpret_cast<const uint4*>(stg + row * 136 + col);
                *reinterpret_cast<uint4*>(P + pb + (size_t)row * Ss + col) = vv;
            }
        }
    }
}

// ---------------------------------------------------------------------------
// Fused colsum + V scale/transpose.  grid (64,8) x 256
// ---------------------------------------------------------------------------
__global__ __launch_bounds__(256) void scale_v_t_kernel(
    const float* __restrict__ v, const float* __restrict__ part,
    __half* __restrict__ tH)
{
    __shared__ float ts[64][65];
    __shared__ float wsum[4][64];
    __shared__ float winv_s[64];
    const int tid = threadIdx.x, bh = blockIdx.y, b = bh >> 2, h = bh & 3;
    const int j0 = blockIdx.x * 64;

    {
        const int j = tid & 63, cq = tid >> 6;
        const float* p = part + (size_t)bh * 128 * Ss + (size_t)cq * 32 * Ss + j0 + j;
        float s = 0.f;
        #pragma unroll
        for (int c = 0; c < 32; c++) s += p[(size_t)c * Ss];
        wsum[cq][j] = s;
    }
    {
        const int j = tid >> 2, c0 = (tid & 3) * 16;
        const float* src = v + ((size_t)(b * Ss + j0 + j)) * Gg + h * DKk + c0;
        #pragma unroll
        for (int u = 0; u < 4; u++) {
            float4 f = *reinterpret_cast<const float4*>(src + u * 4);
            ts[j][c0 + 4*u]     = f.x; ts[j][c0 + 4*u + 1] = f.y;
            ts[j][c0 + 4*u + 2] = f.z; ts[j][c0 + 4*u + 3] = f.w;
        }
    }
    __syncthreads();
    if (tid < 64)
        winv_s[tid] = 1.0f / (((wsum[0][tid] + wsum[1][tid])
                             + (wsum[2][tid] + wsum[3][tid])));
    __syncthreads();

    const int d = tid >> 2, jj0 = (tid & 3) * 16;
    const size_t ob = (((size_t)bh) * DKk + d) * Ss + j0 + jj0;
    __half hbuf[16];
    #pragma unroll
    for (int u = 0; u < 16; u++)
        hbuf[u] = __float2half_rn(ts[jj0 + u][d] * winv_s[jj0 + u] * VSCALE);
    #pragma unroll
    for (int u = 0; u < 2; u++)
        *reinterpret_cast<uint4*>(tH + ob + u * 8) = reinterpret_cast<uint4*>(hbuf)[u];
}

// ---------------------------------------------------------------------------
// pv: Att = (P @ Vw^T)/4096, single fp16 MMA pass, 128x64 CTA tile.
// grid (32,8), 256 thr, smem 36864 B.
// ---------------------------------------------------------------------------
__global__ __launch_bounds__(256) void pv_wm_kernel(
    const __half* __restrict__ P, const __half* __restrict__ vt,
    __nv_bfloat16* __restrict__ atth, __nv_bfloat16* __restrict__ attl)
{
    extern __shared__ char sm[];
    const int PH = 0, VH = 18432;
    const int tid = threadIdx.x, lane = tid & 31, wid = tid >> 5;
    const int wm = wid >> 1, wn = wid & 1;
    const int bh = blockIdx.y, b = bh >> 2, h = bh & 3;
    const int i0 = blockIdx.x * 128;
    const int qr = lane >> 2, qc = lane & 3;

    const int prow = tid >> 1, phalf = tid & 1;
    const __half* pS = P + ((size_t)bh * Ss + i0 + prow) * Ss + phalf * 32;
    const unsigned pso = prow * 144 + phalf * 64;
    const int vrow = tid >> 2, vq = tid & 3;
    const __half* vS = vt + ((size_t)bh * DKk + vrow) * Ss + vq * 16;
    const unsigned vso = VH + vrow * 144 + vq * 32;

    const unsigned base = smem_u32(sm);
    const unsigned aoff = (wm * 32 + (lane & 15)) * 144 + ((lane >> 4) * 8) * 2;
    const unsigned boff = (wn * 32 + ((lane >> 4) & 1) * 8 + (lane & 7)) * 144
                        + (((lane >> 3) & 1) * 8) * 2;

    float acc[2][4][4] = {};
    uint4 rp[4], rv[2];

    #pragma unroll
    for (int u = 0; u < 4; u++) rp[u] = reinterpret_cast<const uint4*>(pS)[u];
    rv[0] = reinterpret_cast<const uint4*>(vS)[0];
    rv[1] = reinterpret_cast<const uint4*>(vS)[1];

    for (int c = 0; c < 64; c++) {
        #pragma unroll
        for (int u = 0; u < 4; u++)
            *reinterpret_cast<uint4*>(sm + PH + pso + u * 16) = rp[u];
        *reinterpret_cast<uint4*>(sm + vso)      = rv[0];
        *reinterpret_cast<uint4*>(sm + vso + 16) = rv[1];
        __syncthreads();

        if (c < 63) {
            const size_t go = (size_t)(c + 1) * 64;
            #pragma unroll
            for (int u = 0; u < 4; u++)
                rp[u] = reinterpret_cast<const uint4*>(pS + go)[u];
            rv[0] = reinterpret_cast<const uint4*>(vS + go)[0];
            rv[1] = reinterpret_cast<const uint4*>(vS + go)[1];
        }

        #pragma unroll
        for (int kk = 0; kk < 4; kk++) {
            unsigned aH[2][4], bH[2][4];
            #pragma unroll
            for (int mt = 0; mt < 2; mt++) {
                const unsigned ad = base + PH + aoff + mt * 2304 + kk * 32;
                ldsm4(aH[mt][0], aH[mt][1], aH[mt][2], aH[mt][3], ad);
            }
            #pragma unroll
            for (int g = 0; g < 2; g++) {
                const unsigned bd = base + VH + boff + g * 2304 + kk * 32;
                ldsm4(bH[g][0], bH[g][1], bH[g][2], bH[g][3], bd);
            }
            #pragma unroll
            for (int mt = 0; mt < 2; mt++)
                #pragma unroll
                for (int nt = 0; nt < 4; nt++)
                    mma_f16(acc[mt][nt], aH[mt], &bH[nt >> 1][(nt & 1) * 2]);
        }
        __syncthreads();
    }

    __nv_bfloat16* sh = reinterpret_cast<__nv_bfloat16*>(sm);            // stride 72
    __nv_bfloat16* sl = reinterpret_cast<__nv_bfloat16*>(sm + 18432);
    #pragma unroll
    for (int mt = 0; mt < 2; mt++) {
        const int r0 = wm * 32 + mt * 16 + qr;
        #pragma unroll
        for (int nt = 0; nt < 4; nt++) {
            const int col = wn * 32 + nt * 8 + qc * 2;
            #pragma unroll
            for (int pr = 0; pr < 2; pr++) {
                unsigned hv, lv;
                split2(acc[mt][nt][pr * 2] * OSCALE,
                       acc[mt][nt][pr * 2 + 1] * OSCALE, hv, lv);
                *reinterpret_cast<unsigned*>(sh + (r0 + pr * 8) * 72 + col) = hv;
                *reinterpret_cast<unsigned*>(sl + (r0 + pr * 8) * 72 + col) = lv;
            }
        }
    }
    __syncthreads();
    #pragma unroll
    for (int ps = 0; ps < 4; ps++) {
        const int idx = ps * 2048 + tid * 8;
        const int row = idx >> 6, col = idx & 63;
        uint4 hv = *reinterpret_cast<const uint4*>(sh + row * 72 + col);
        uint4 lv = *reinterpret_cast<const uint4*>(sl + row * 72 + col);
        const size_t o = ((size_t)(b * Ss + i0 + row)) * Gg + h * DKk + col;
        *reinterpret_cast<uint4*>(atth + o) = hv;
        *reinterpret_cast<uint4*>(attl + o) = lv;
    }
}

// ---------------------------------------------------------------------------
extern "C" void kernel_launch(void* const* d_in, const int* in_sizes, int n_in,
                              void* d_out, int out_size)
{
    const float* x  = (const float*)d_in[0];
    const float* wq = (const float*)d_in[1];
    const float* bq = (const float*)d_in[2];
    const float* wk = (const float*)d_in[3];
    const float* bk = (const float*)d_in[4];
    const float* wv = (const float*)d_in[5];
    const float* bv = (const float*)d_in[6];
    const float* wo = (const float*)d_in[7];
    const float* bo = (const float*)d_in[8];
    float* out = (float*)d_out;

    __half *x16, *w16, *q16, *k16, *p, *vt;
    __nv_bfloat16 *xvh, *xvl, *wvh, *wvl, *atth, *attl;
    float *v, *part;
    cudaGetSymbolAddress((void**)&x16, g_x16);
    cudaGetSymbolAddress((void**)&xvh, g_xvh);  cudaGetSymbolAddress((void**)&xvl, g_xvl);
    cudaGetSymbolAddress((void**)&w16, g_w16);
    cudaGetSymbolAddress((void**)&wvh, g_wvh);  cudaGetSymbolAddress((void**)&wvl, g_wvl);
    cudaGetSymbolAddress((void**)&q16, g_q16);  cudaGetSymbolAddress((void**)&k16, g_k16);
    cudaGetSymbolAddress((void**)&v,   g_v);
    cudaGetSymbolAddress((void**)&p,   g_p);
    cudaGetSymbolAddress((void**)&part,g_part);
    cudaGetSymbolAddress((void**)&vt,  g_vt);
    cudaGetSymbolAddress((void**)&atth,g_atth); cudaGetSymbolAddress((void**)&attl,g_attl);

    const int SC_SMEM = 54272;
    const int PV_SMEM = 36864;
    const int TC_SMEM = 55552;
    const int QK_SMEM = 27904;
    cudaFuncSetAttribute(scores_wm_kernel, cudaFuncAttributeMaxDynamicSharedMemorySize, SC_SMEM);
    cudaFuncSetAttribute(pv_wm_kernel,     cudaFuncAttributeMaxDynamicSharedMemorySize, PV_SMEM);
    cudaFuncSetAttribute(gemm_qk_kernel,   cudaFuncAttributeMaxDynamicSharedMemorySize, QK_SMEM);
    cudaFuncSetAttribute(gemm_out_kernel,  cudaFuncAttributeMaxDynamicSharedMemorySize, TC_SMEM);

    // fused splits
    split_all_kernel<<<6400, 256>>>(x, wq, wk, wv, wo,
                                    x16, xvh, xvl, w16, wvh, wvl);

    // projections
    gemm_qk_kernel<<<dim3(4, 64, 2), 256, QK_SMEM>>>(x16, w16, bq, bk, q16, k16);
    gemm_out_kernel<<<dim3(4, 64), 256, TC_SMEM>>>(xvh, xvl, wvh, wvl, bv, v);

    // attention
    scores_wm_kernel<<<dim3(32, 32, 8), 256, SC_SMEM>>>(q16, k16, p, part);
    scale_v_t_kernel<<<dim3(64, 8), 256>>>(v, part, vt);
    pv_wm_kernel<<<dim3(32, 8), 256, PV_SMEM>>>(p, vt, atth, attl);

    // out projection
    gemm_out_kernel<<<dim3(4, 64), 256, TC_SMEM>>>(atth, attl,
        wvh + WN, wvl + WN, bo, out);
}